// round 16
// baseline (speedup 1.0000x reference)
#include <cuda_runtime.h>
#include <cuda_fp16.h>
#include <math.h>
#include <stdint.h>

#define BB 4
#define LL 4096
#define HH 1024
#define SELK 512
#define WWIN 256
#define NWIN 16
#define WTOK 2176
#define SCALE_ATT 0.125f

typedef __half h16;

// ---------------- scratch ----------------
__device__ __align__(128) h16  g_hsh[BB * LL * HH];
// window branch
__device__ __align__(128) h16  g_qk[BB * WTOK * 2048];
__device__ __align__(128) h16  g_vt[BB * WTOK * HH];
__device__ __align__(128) float g_SW[BB * NWIN * WWIN * WWIN];
__device__ __align__(128) h16  g_pW[BB * NWIN * WWIN * WWIN];
__device__ __align__(128) h16  g_att[BB * LL * HH];
__device__ __align__(128) float g_O[BB * LL * HH];
// compressed branch
__device__ __align__(128) h16  g_comp[BB * 1024 * HH];
__device__ __align__(128) h16  g_qkC[BB * 1024 * 2048];
__device__ __align__(128) h16  g_vtC[BB * HH * 1024];
__device__ __align__(128) float g_SC[BB * 1024 * 1024];
__device__ __align__(128) h16  g_pC[BB * 1024 * 1024];
__device__ __align__(128) h16  g_attC[BB * 1024 * HH];
__device__ __align__(128) float g_O2[BB * 1024 * HH];
// selected branch
__device__ __align__(128) h16  g_sel[BB * SELK * HH];
__device__ __align__(128) h16  g_qkS[BB * SELK * 2048];
__device__ __align__(128) h16  g_vtS[BB * HH * SELK];
__device__ __align__(128) float g_SS[BB * SELK * SELK];
__device__ __align__(128) h16  g_pS[BB * SELK * SELK];
__device__ __align__(128) h16  g_attS[BB * SELK * HH];
__device__ __align__(128) float g_O3[BB * SELK * HH];
// misc
__device__ __align__(128) float g_gates[BB * LL * 3];
__device__ __align__(128) float g_scr[BB * LL];
__device__ __align__(128) int   g_idx[BB * SELK];
__device__ __align__(128) h16  g_WqkT[2 * HH * HH];
__device__ __align__(128) float g_bqk[2 * HH];
__device__ __align__(128) h16  g_WvT[HH * HH];
__device__ __align__(128) h16  g_WoT[3 * HH * HH];
__device__ __align__(128) h16  g_WcT[4 * HH * HH];

// ---------------- PTX helpers ----------------
__device__ __forceinline__ uint32_t smem_u32(const void* p) {
    uint32_t a;
    asm("{ .reg .u64 t; cvta.to.shared.u64 t, %1; cvt.u32.u64 %0, t; }" : "=r"(a) : "l"(p));
    return a;
}
#define LDSM4(r, a) \
    asm volatile("ldmatrix.sync.aligned.m8n8.x4.shared.b16 {%0,%1,%2,%3}, [%4];" \
        : "=r"((r)[0]), "=r"((r)[1]), "=r"((r)[2]), "=r"((r)[3]) : "r"(a))
#define MMAF16(c, a, b0, b1) \
    asm volatile("mma.sync.aligned.m16n8k16.row.col.f32.f16.f16.f32 " \
        "{%0,%1,%2,%3}, {%4,%5,%6,%7}, {%8,%9}, {%0,%1,%2,%3};" \
        : "+f"((c)[0]), "+f"((c)[1]), "+f"((c)[2]), "+f"((c)[3]) \
        : "r"((a)[0]), "r"((a)[1]), "r"((a)[2]), "r"((a)[3]), "r"(b0), "r"(b1))
#define CP16(s, g) asm volatile("cp.async.cg.shared.global [%0], [%1], 16;" :: "r"(s), "l"(g))
#define CP_COMMIT() asm volatile("cp.async.commit_group;" ::: "memory")
#define CP_WAIT1()  asm volatile("cp.async.wait_group 1;" ::: "memory")
#define CP_WAIT0()  asm volatile("cp.async.wait_group 0;" ::: "memory")

// ---------------- fp16 tensor GEMM via mma.sync (KC=128, 1 CTA/SM) ----------------
#define KC 128
#define ROWB 272
#define MATB (128 * ROWB)        // 34816
#define STAGEB (2 * MATB)        // 69632
#define SMEM_DYN (3 * STAGEB)    // 208896

__global__ __launch_bounds__(256)
void tgemm_kernel(const h16* __restrict__ A, const h16* __restrict__ B,
                  float* __restrict__ C, h16* __restrict__ Ch,
                  const float* __restrict__ bias, int biasMode,
                  const float* __restrict__ gates, int gateCol,
                  int K, int lda, int ldb, int ldc, int inner,
                  long sA1, long sA2, long sB1, long sB2, long sC1, long sC2,
                  long sG1, long sG2, float scale, int accFlag)
{
    extern __shared__ __align__(128) char dsm[];
    const int tid = threadIdx.x;
    const int wid = tid >> 5, lane = tid & 31;
    const int z = blockIdx.z, zo = z / inner, zi = z - zo * inner;
    A += zo * sA1 + zi * sA2;
    B += zo * sB1 + zi * sB2;
    const long cOff = zo * sC1 + zi * sC2;
    const long gOff = zo * sG1 + zi * sG2;
    const int m0 = blockIdx.y * 128, n0 = blockIdx.x * 128;

    const uint32_t sbase = smem_u32(dsm);
    const int mw = wid >> 2, nw = wid & 3;
    const int m_base = mw * 64, n_base = nw * 32;

    float acc[4][4][4];
#pragma unroll
    for (int i = 0; i < 4; i++)
#pragma unroll
        for (int j = 0; j < 4; j++)
#pragma unroll
            for (int c = 0; c < 4; c++) acc[i][j][c] = 0.f;

    const int nc = K / KC;

    auto load_chunk = [&](int ch, int s) {
        const int kt = ch * KC;
        const uint32_t sb = sbase + s * STAGEB;
#pragma unroll
        for (int it = 0; it < 16; it++) {
            const int idx = it * 256 + tid;
            const int mat = idx >> 11;
            const int rem = idx & 2047;
            const int r = rem >> 4, j = rem & 15;
            const h16* src = mat ? (B + (long)(n0 + r) * ldb + kt + j * 8)
                                 : (A + (long)(m0 + r) * lda + kt + j * 8);
            CP16(sb + mat * MATB + r * ROWB + j * 16, src);
        }
    };

    load_chunk(0, 0);
    CP_COMMIT();
    if (nc > 1) { load_chunk(1, 1); CP_COMMIT(); }

    const uint32_t aOff = (uint32_t)((m_base + (lane & 15)) * ROWB + (lane >> 4) * 16);
    const uint32_t bOff = (uint32_t)((n_base + (lane & 7) + (((lane >> 4) & 1) << 3)) * ROWB
                                     + ((lane >> 3) & 1) * 16);

    for (int ch = 0; ch < nc; ch++) {
        const int s = ch - (ch / 3) * 3;
        if (ch + 1 < nc) CP_WAIT1(); else CP_WAIT0();
        __syncthreads();
        if (ch + 2 < nc) {
            load_chunk(ch + 2, (ch + 2) - ((ch + 2) / 3) * 3);
            CP_COMMIT();
        }
        const uint32_t aB = sbase + s * STAGEB + aOff;
        const uint32_t bB = sbase + s * STAGEB + MATB + bOff;
#pragma unroll
        for (int ks = 0; ks < 8; ks++) {
            uint32_t ah[4][4], bh[2][4];
#pragma unroll
            for (int mt = 0; mt < 4; mt++)
                LDSM4(ah[mt], aB + mt * (16 * ROWB) + ks * 32);
#pragma unroll
            for (int g = 0; g < 2; g++)
                LDSM4(bh[g], bB + g * (16 * ROWB) + ks * 32);
#pragma unroll
            for (int mt = 0; mt < 4; mt++)
#pragma unroll
                for (int nt = 0; nt < 4; nt++) {
                    const int g = nt >> 1, o = (nt & 1) << 1;
                    MMAF16(acc[mt][nt], ah[mt], bh[g][o], bh[g][o + 1]);
                }
        }
    }

    // epilogue
    const int tq = lane & 3, rq = lane >> 2;
#pragma unroll
    for (int mt = 0; mt < 4; mt++) {
#pragma unroll
        for (int half = 0; half < 2; half++) {
            const int rl = m0 + m_base + mt * 16 + rq + half * 8;
            float g = 1.f;
            if (gates) g = gates[gOff + (long)rl * 3 + gateCol];
            float rb = 0.f;
            if (biasMode == 2) rb = bias[rl];
#pragma unroll
            for (int nt = 0; nt < 4; nt++) {
                const int cl = n_base + nt * 8 + tq * 2;
                float v0 = acc[mt][nt][half * 2 + 0] * scale * g;
                float v1 = acc[mt][nt][half * 2 + 1] * scale * g;
                if (biasMode == 1) { v0 += bias[n0 + cl]; v1 += bias[n0 + cl + 1]; }
                else if (biasMode == 2) { v0 += rb; v1 += rb; }
                const long co = cOff + (long)rl * ldc + n0 + cl;
                if (C) {
                    if (accFlag) {
                        const float2 o = *(const float2*)(C + co);
                        v0 += o.x; v1 += o.y;
                    }
                    float2 w; w.x = v0; w.y = v1;
                    *(float2*)(C + co) = w;
                }
                if (Ch) {
                    __align__(4) h16 hv[2];
                    hv[0] = __float2half_rn(v0);
                    hv[1] = __float2half_rn(v1);
                    *(uint32_t*)(Ch + co) = *(uint32_t*)hv;
                }
            }
        }
    }
}

// ---------------- reductions ----------------
__device__ __forceinline__ float warp_sum(float v) {
#pragma unroll
    for (int o = 16; o > 0; o >>= 1) v += __shfl_xor_sync(0xffffffffu, v, o);
    return v;
}
__device__ __forceinline__ float warp_max(float v) {
#pragma unroll
    for (int o = 16; o > 0; o >>= 1) v = fmaxf(v, __shfl_xor_sync(0xffffffffu, v, o));
    return v;
}
__device__ __forceinline__ float blk_sum(float v, float* sh) {
    v = warp_sum(v);
    __syncthreads();
    if ((threadIdx.x & 31) == 0) sh[threadIdx.x >> 5] = v;
    __syncthreads();
    float r = 0.f;
    const int nw = blockDim.x >> 5;
    for (int i = 0; i < nw; i++) r += sh[i];
    return r;
}

// ---------------- fused pre ----------------
__global__ __launch_bounds__(256)
void pre_kernel(const float* __restrict__ hs, const float* __restrict__ Wg,
                const float* __restrict__ bg, const float* __restrict__ Ws,
                const float* __restrict__ bs, const float* __restrict__ bq,
                const float* __restrict__ bk, float* __restrict__ gates,
                float* __restrict__ scr, h16* __restrict__ hsh,
                float* __restrict__ bqk)
{
    __shared__ float sW[4 * HH];
    for (int i = threadIdx.x; i < 3 * HH; i += 256) sW[i] = Wg[i];
    for (int i = threadIdx.x; i < HH; i += 256) sW[3 * HH + i] = Ws[i];
    if (blockIdx.x == 0)
        for (int i = threadIdx.x; i < HH; i += 256) { bqk[i] = bq[i]; bqk[HH + i] = bk[i]; }
    __syncthreads();

    const int wid = threadIdx.x >> 5, lane = threadIdx.x & 31;
    const long row = (long)blockIdx.x * 8 + wid;
    const float4* x = (const float4*)(hs + row * HH);
    uint2* y = (uint2*)(hsh + row * HH);
    float a0 = 0, a1 = 0, a2 = 0, as = 0;
#pragma unroll
    for (int k = 0; k < 8; k++) {
        const float4 v = x[lane + k * 32];
        const int e = 4 * (lane + k * 32);
        a0 += v.x * sW[e * 3] + v.y * sW[e * 3 + 3] + v.z * sW[e * 3 + 6] + v.w * sW[e * 3 + 9];
        a1 += v.x * sW[e * 3 + 1] + v.y * sW[e * 3 + 4] + v.z * sW[e * 3 + 7] + v.w * sW[e * 3 + 10];
        a2 += v.x * sW[e * 3 + 2] + v.y * sW[e * 3 + 5] + v.z * sW[e * 3 + 8] + v.w * sW[e * 3 + 11];
        as += v.x * sW[3 * HH + e] + v.y * sW[3 * HH + e + 1]
            + v.z * sW[3 * HH + e + 2] + v.w * sW[3 * HH + e + 3];
        __align__(8) h16 hv[4];
        hv[0] = __float2half_rn(v.x); hv[1] = __float2half_rn(v.y);
        hv[2] = __float2half_rn(v.z); hv[3] = __float2half_rn(v.w);
        y[lane + k * 32] = *(uint2*)hv;
    }
    a0 = warp_sum(a0); a1 = warp_sum(a1); a2 = warp_sum(a2); as = warp_sum(as);
    if (lane == 0) {
        const float g0 = 1.f / (1.f + expf(-(a0 + bg[0])));
        const float g1 = 1.f / (1.f + expf(-(a1 + bg[1])));
        const float g2 = 1.f / (1.f + expf(-(a2 + bg[2])));
        const float s = g0 + g1 + g2 + 1e-6f;
        gates[row * 3 + 0] = g0 / s;
        gates[row * 3 + 1] = g1 / s;
        gates[row * 3 + 2] = g2 / s;
        scr[row] = as + bs[0];
    }
}

__global__ void ttrans_kernel(const float* __restrict__ W, h16* __restrict__ o,
                              int K, int N)
{
    __shared__ float t[32][33];
    const int bx = blockIdx.x * 32;
    const int by = blockIdx.y * 32;
    const int tx = threadIdx.x, ty = threadIdx.y;
#pragma unroll
    for (int j = 0; j < 32; j += 8) t[ty + j][tx] = W[(long)(by + ty + j) * N + bx + tx];
    __syncthreads();
#pragma unroll
    for (int j = 0; j < 32; j += 8)
        o[(long)(bx + ty + j) * K + by + tx] = __float2half_rn(t[tx][ty + j]);
}

__global__ void topk_kernel(const float* __restrict__ score, int* __restrict__ idx)
{
    const int b = blockIdx.x;
    const int tid = threadIdx.x;
    __shared__ unsigned s_key[4096];
    __shared__ int s_cnt;
    __shared__ int s_sA[1024];
    __shared__ int s_sE[1024];

#pragma unroll
    for (int j = 0; j < 4; j++) {
        const int i = tid * 4 + j;
        unsigned u = __float_as_uint(score[b * 4096 + i]);
        u = (u & 0x80000000u) ? ~u : (u | 0x80000000u);
        s_key[i] = u;
    }
    __syncthreads();

    unsigned lo = 0u, hi = 0xFFFFFFFFu;
    while (lo < hi) {
        const unsigned mid = (unsigned)((((unsigned long long)lo + hi) + 1ull) >> 1);
        if (tid == 0) s_cnt = 0;
        __syncthreads();
        int c = 0;
#pragma unroll
        for (int j = 0; j < 4; j++) c += (s_key[tid * 4 + j] >= mid) ? 1 : 0;
#pragma unroll
        for (int o = 16; o > 0; o >>= 1) c += __shfl_xor_sync(0xffffffffu, c, o);
        if ((tid & 31) == 0) atomicAdd(&s_cnt, c);
        __syncthreads();
        if (s_cnt >= SELK) lo = mid; else hi = mid - 1;
        __syncthreads();
    }
    const unsigned T = lo;

    unsigned kv[4];
    int aCnt = 0, eCnt = 0;
#pragma unroll
    for (int j = 0; j < 4; j++) {
        kv[j] = s_key[tid * 4 + j];
        aCnt += (kv[j] > T) ? 1 : 0;
        eCnt += (kv[j] == T) ? 1 : 0;
    }
    s_sA[tid] = aCnt; s_sE[tid] = eCnt;
    __syncthreads();
    for (int off = 1; off < 1024; off <<= 1) {
        const int a = (tid >= off) ? s_sA[tid - off] : 0;
        const int e = (tid >= off) ? s_sE[tid - off] : 0;
        __syncthreads();
        s_sA[tid] += a; s_sE[tid] += e;
        __syncthreads();
    }
    const int totalA = s_sA[1023];
    const int need = SELK - totalA;
    int aBef = s_sA[tid] - aCnt;
    int eBef = s_sE[tid] - eCnt;
#pragma unroll
    for (int j = 0; j < 4; j++) {
        if (kv[j] > T) {
            idx[b * SELK + aBef + (eBef < need ? eBef : need)] = tid * 4 + j;
            aBef++;
        } else if (kv[j] == T) {
            if (eBef < need) idx[b * SELK + aBef + eBef] = tid * 4 + j;
            eBef++;
        }
    }
}

__global__ void gather_kernel(const h16* __restrict__ hsh, const int* __restrict__ idx,
                              h16* __restrict__ sel)
{
    const int r = blockIdx.x, b = blockIdx.y;
    const int src = idx[b * SELK + r];
    const uint2* s = (const uint2*)(hsh + ((long)b * LL + src) * HH);
    uint2* d = (uint2*)(sel + ((long)b * SELK + r) * HH);
    d[threadIdx.x] = s[threadIdx.x];
}

__global__ __launch_bounds__(256)
void softmax_kernel(const float* __restrict__ S, h16* __restrict__ P, int N)
{
    const int nf = N >> 7;
    const int wid = threadIdx.x >> 5, lane = threadIdx.x & 31;
    const long row = (long)blockIdx.x * 8 + wid;
    const float4* p = (const float4*)(S + row * N);
    float4 v[8];
    float mx = -1e30f;
#pragma unroll
    for (int k = 0; k < 8; k++) if (k < nf) {
        v[k] = p[lane + k * 32];
        mx = fmaxf(mx, fmaxf(fmaxf(v[k].x, v[k].y), fmaxf(v[k].z, v[k].w)));
    }
    mx = warp_max(mx);
    float s = 0.f;
#pragma unroll
    for (int k = 0; k < 8; k++) if (k < nf) {
        v[k].x = expf(v[k].x - mx); v[k].y = expf(v[k].y - mx);
        v[k].z = expf(v[k].z - mx); v[k].w = expf(v[k].w - mx);
        s += v[k].x + v[k].y + v[k].z + v[k].w;
    }
    s = warp_sum(s);
    const float inv = 1.f / s;
    uint2* o = (uint2*)(P + row * N);
#pragma unroll
    for (int k = 0; k < 8; k++) if (k < nf) {
        __align__(8) h16 hv[4];
        hv[0] = __float2half_rn(v[k].x * inv); hv[1] = __float2half_rn(v[k].y * inv);
        hv[2] = __float2half_rn(v[k].z * inv); hv[3] = __float2half_rn(v[k].w * inv);
        o[lane + k * 32] = *(uint2*)hv;
    }
}

__device__ __forceinline__ void ln_row(float4 v, float* sh, float4* y4, int t)
{
    float s = v.x + v.y + v.z + v.w;
    s = blk_sum(s, sh);
    const float mu = s * (1.f / HH);
    float q = (v.x - mu) * (v.x - mu) + (v.y - mu) * (v.y - mu)
            + (v.z - mu) * (v.z - mu) + (v.w - mu) * (v.w - mu);
    __syncthreads();
    q = blk_sum(q, sh);
    const float inv = rsqrtf(q * (1.f / HH) + 1e-6f);
    float4 r;
    r.x = (v.x - mu) * inv; r.y = (v.y - mu) * inv;
    r.z = (v.z - mu) * inv; r.w = (v.w - mu) * inv;
    y4[t] = r;
}

__global__ __launch_bounds__(256)
void ln_hi_kernel(const float* __restrict__ O, const float* __restrict__ hs,
                  float* __restrict__ out)
{
    const long blk = blockIdx.x;
    const long b = blk / 3072, r = blk - b * 3072;
    const long row = b * LL + 1024 + r;
    const int t = threadIdx.x;
    __shared__ float sh[8];
    const float4 a = ((const float4*)(O + row * HH))[t];
    const float4 bx = ((const float4*)(hs + row * HH))[t];
    float4 v;
    v.x = a.x * 0.5f + bx.x * 0.5f;
    v.y = a.y * 0.5f + bx.y * 0.5f;
    v.z = a.z * 0.5f + bx.z * 0.5f;
    v.w = a.w * 0.5f + bx.w * 0.5f;
    ln_row(v, sh, (float4*)(out + row * HH), t);
}

__global__ __launch_bounds__(256)
void ln_lo_kernel(const float* __restrict__ O, const float* __restrict__ O2,
                  const float* __restrict__ O3, const float* __restrict__ hs,
                  float* __restrict__ out)
{
    const long blk = blockIdx.x;
    const long b = blk >> 10, l = blk & 1023;
    const long row = b * LL + l;
    const int t = threadIdx.x;
    __shared__ float sh[8];
    float4 a = ((const float4*)(O + row * HH))[t];
    {
        const float4 c = ((const float4*)(O2 + (b * 1024 + l) * HH))[t];
        a.x += c.x; a.y += c.y; a.z += c.z; a.w += c.w;
    }
    if (l < 512) {
        const float4 c = ((const float4*)(O3 + (b * 512 + l) * HH))[t];
        a.x += c.x; a.y += c.y; a.z += c.z; a.w += c.w;
    }
    const float4 bx = ((const float4*)(hs + row * HH))[t];
    float4 v;
    v.x = a.x * 0.5f + bx.x * 0.5f;
    v.y = a.y * 0.5f + bx.y * 0.5f;
    v.z = a.z * 0.5f + bx.z * 0.5f;
    v.w = a.w * 0.5f + bx.w * 0.5f;
    ln_row(v, sh, (float4*)(out + row * HH), t);
}

// ---------------- host dispatch ----------------
static void TG(cudaStream_t st, const h16* A, const h16* B, float* C, h16* Ch,
               const float* bias, int biasMode, const float* gates, int gateCol,
               int M, int N, int K, int lda, int ldb, int ldc, int nz, int inner,
               long sA1, long sA2, long sB1, long sB2, long sC1, long sC2,
               long sG1, long sG2, float scale, int acc)
{
    dim3 grid(N / 128, M / 128, nz);
    tgemm_kernel<<<grid, 256, SMEM_DYN, st>>>(A, B, C, Ch, bias, biasMode, gates, gateCol,
                                              K, lda, ldb, ldc, inner,
                                              sA1, sA2, sB1, sB2, sC1, sC2,
                                              sG1, sG2, scale, acc);
}

extern "C" void kernel_launch(void* const* d_in, const int* in_sizes, int n_in,
                              void* d_out, int out_size)
{
    const float* hs = (const float*)d_in[0];
    const float* Wq = (const float*)d_in[1];
    const float* bq = (const float*)d_in[2];
    const float* Wk = (const float*)d_in[3];
    const float* bk = (const float*)d_in[4];
    const float* Wv = (const float*)d_in[5];
    const float* bv = (const float*)d_in[6];
    const float* Wo = (const float*)d_in[7];
    const float* bo = (const float*)d_in[8];
    const float* Wg = (const float*)d_in[9];
    const float* bg = (const float*)d_in[10];
    const float* Wc = (const float*)d_in[11];
    const float* bc = (const float*)d_in[12];
    const float* Ws = (const float*)d_in[13];
    const float* bs = (const float*)d_in[14];
    float* out = (float*)d_out;

    static int inited = 0;
    static cudaStream_t st1, st2;
    static cudaEvent_t evS, evPre, evQK, evWv, evWo, evV, ev1, ev2;
    if (!inited) {
        cudaFuncSetAttribute(tgemm_kernel, cudaFuncAttributeMaxDynamicSharedMemorySize, SMEM_DYN);
        cudaStreamCreateWithFlags(&st1, cudaStreamNonBlocking);
        cudaStreamCreateWithFlags(&st2, cudaStreamNonBlocking);
        cudaEventCreateWithFlags(&evS, cudaEventDisableTiming);
        cudaEventCreateWithFlags(&evPre, cudaEventDisableTiming);
        cudaEventCreateWithFlags(&evQK, cudaEventDisableTiming);
        cudaEventCreateWithFlags(&evWv, cudaEventDisableTiming);
        cudaEventCreateWithFlags(&evWo, cudaEventDisableTiming);
        cudaEventCreateWithFlags(&evV, cudaEventDisableTiming);
        cudaEventCreateWithFlags(&ev1, cudaEventDisableTiming);
        cudaEventCreateWithFlags(&ev2, cudaEventDisableTiming);
        inited = 1;
    }
    cudaStream_t st0 = 0;

    h16 *hsh, *qk, *vt, *pW, *att, *comp, *qkC, *vtC, *pC, *attC;
    h16 *sel, *qkS, *vtS, *pS, *attS, *WqkT, *WvT, *WoT, *WcT;
    float *SW, *SC, *SS, *O, *O2, *O3, *gates, *scr, *bqk;
    int* idx;
    cudaGetSymbolAddress((void**)&hsh, g_hsh);
    cudaGetSymbolAddress((void**)&qk, g_qk);
    cudaGetSymbolAddress((void**)&vt, g_vt);
    cudaGetSymbolAddress((void**)&SW, g_SW);
    cudaGetSymbolAddress((void**)&pW, g_pW);
    cudaGetSymbolAddress((void**)&att, g_att);
    cudaGetSymbolAddress((void**)&O, g_O);
    cudaGetSymbolAddress((void**)&comp, g_comp);
    cudaGetSymbolAddress((void**)&qkC, g_qkC);
    cudaGetSymbolAddress((void**)&vtC, g_vtC);
    cudaGetSymbolAddress((void**)&SC, g_SC);
    cudaGetSymbolAddress((void**)&pC, g_pC);
    cudaGetSymbolAddress((void**)&attC, g_attC);
    cudaGetSymbolAddress((void**)&O2, g_O2);
    cudaGetSymbolAddress((void**)&sel, g_sel);
    cudaGetSymbolAddress((void**)&qkS, g_qkS);
    cudaGetSymbolAddress((void**)&vtS, g_vtS);
    cudaGetSymbolAddress((void**)&SS, g_SS);
    cudaGetSymbolAddress((void**)&pS, g_pS);
    cudaGetSymbolAddress((void**)&attS, g_attS);
    cudaGetSymbolAddress((void**)&O3, g_O3);
    cudaGetSymbolAddress((void**)&gates, g_gates);
    cudaGetSymbolAddress((void**)&scr, g_scr);
    cudaGetSymbolAddress((void**)&idx, g_idx);
    cudaGetSymbolAddress((void**)&WqkT, g_WqkT);
    cudaGetSymbolAddress((void**)&bqk, g_bqk);
    cudaGetSymbolAddress((void**)&WvT, g_WvT);
    cudaGetSymbolAddress((void**)&WoT, g_WoT);
    cudaGetSymbolAddress((void**)&WcT, g_WcT);

    dim3 tb(32, 8);
    // legal fork
    cudaEventRecord(evS, st0);
    cudaStreamWaitEvent(st1, evS, 0);
    cudaStreamWaitEvent(st2, evS, 0);

    // st1: weight transposes first (off critical path)
    ttrans_kernel<<<dim3(HH / 32, HH / 32), tb, 0, st1>>>(Wq, WqkT, HH, HH);
    ttrans_kernel<<<dim3(HH / 32, HH / 32), tb, 0, st1>>>(Wk, WqkT + HH * HH, HH, HH);
    cudaEventRecord(evQK, st1);
    for (int r = 0; r < 3; r++)
        ttrans_kernel<<<dim3(HH / 32, HH / 32), tb, 0, st1>>>(Wo + (long)r * HH * HH,
                                                              WoT + (long)r * HH * HH, HH, HH);
    cudaEventRecord(evWo, st1);
    ttrans_kernel<<<dim3(HH / 32, 4 * HH / 32), tb, 0, st1>>>(Wc, WcT, 4 * HH, HH);

    // st2: Wv transpose
    ttrans_kernel<<<dim3(HH / 32, HH / 32), tb, 0, st2>>>(Wv, WvT, HH, HH);
    cudaEventRecord(evWv, st2);

    // st0: ONLY pre on the critical-path head
    pre_kernel<<<(BB * LL) / 8, 256, 0, st0>>>(hs, Wg, bg, Ws, bs, bq, bk, gates, scr, hsh, bqk);
    cudaEventRecord(evPre, st0);

    // st0: window QK GEMM
    cudaStreamWaitEvent(st0, evQK, 0);
    TG(st0, hsh, WqkT, nullptr, qk, bqk, 1, nullptr, 0,
       WTOK, 2048, HH, HH, HH, 2048, BB, 1,
       (long)LL * HH, 0, 0, 0, (long)WTOK * 2048, 0, 0, 0, 1.f, 0);

    // st2: window V, then topk/gather + sel branch
    cudaStreamWaitEvent(st2, evPre, 0);
    TG(st2, WvT, hsh, nullptr, vt, bv, 2, nullptr, 0,
       HH, WTOK, HH, HH, HH, WTOK, BB, 1,
       0, 0, (long)LL * HH, 0, (long)HH * WTOK, 0, 0, 0, 1.f, 0);
    cudaEventRecord(evV, st2);
    topk_kernel<<<BB, 1024, 0, st2>>>(scr, idx);
    gather_kernel<<<dim3(SELK, BB), 256, 0, st2>>>(hsh, idx, sel);
    cudaStreamWaitEvent(st2, evQK, 0);
    TG(st2, sel, WqkT, nullptr, qkS, bqk, 1, nullptr, 0,
       BB * SELK, 2048, HH, HH, HH, 2048, 1, 1, 0, 0, 0, 0, 0, 0, 0, 0, 1.f, 0);
    TG(st2, WvT, sel, nullptr, vtS, bv, 2, nullptr, 0,
       HH, SELK, HH, HH, HH, SELK, BB, 1,
       0, 0, (long)SELK * HH, 0, (long)HH * SELK, 0, 0, 0, 1.f, 0);
    TG(st2, qkS, qkS + 1024, SS, nullptr, nullptr, 0, nullptr, 0,
       SELK, SELK, HH, 2048, 2048, SELK, BB, 1,
       (long)SELK * 2048, 0, (long)SELK * 2048, 0, (long)SELK * SELK, 0, 0, 0,
       SCALE_ATT, 0);
    softmax_kernel<<<(BB * SELK) / 8, 256, 0, st2>>>(SS, pS, SELK);
    TG(st2, pS, vtS, nullptr, attS, nullptr, 0, gates, 1,
       SELK, HH, SELK, SELK, SELK, HH, BB, 1,
       (long)SELK * SELK, 0, (long)HH * SELK, 0, (long)SELK * HH, 0,
       (long)LL * 3, 0, 1.f, 0);
    cudaStreamWaitEvent(st2, evWo, 0);
    TG(st2, attS, WoT + HH * HH, O3, nullptr, nullptr, 0, nullptr, 0,
       SELK, HH, HH, HH, HH, HH, BB, 1,
       (long)SELK * HH, 0, 0, 0, (long)SELK * HH, 0, 0, 0, 1.f, 0);
    cudaEventRecord(ev2, st2);

    // st1: comp branch
    cudaStreamWaitEvent(st1, evPre, 0);
    TG(st1, hsh, WcT, nullptr, comp, bc, 1, nullptr, 0,
       BB * 1024, HH, 4 * HH, 4 * HH, 4 * HH, HH, 1, 1,
       0, 0, 0, 0, 0, 0, 0, 0, 1.f, 0);
    TG(st1, comp, WqkT, nullptr, qkC, bqk, 1, nullptr, 0,
       BB * 1024, 2048, HH, HH, HH, 2048, 1, 1, 0, 0, 0, 0, 0, 0, 0, 0, 1.f, 0);
    cudaStreamWaitEvent(st1, evWv, 0);
    TG(st1, WvT, comp, nullptr, vtC, bv, 2, nullptr, 0,
       HH, 1024, HH, HH, HH, 1024, BB, 1,
       0, 0, (long)1024 * HH, 0, (long)HH * 1024, 0, 0, 0, 1.f, 0);
    TG(st1, qkC, qkC + 1024, SC, nullptr, nullptr, 0, nullptr, 0,
       1024, 1024, HH, 2048, 2048, 1024, BB, 1,
       (long)1024 * 2048, 0, (long)1024 * 2048, 0, (long)1024 * 1024, 0, 0, 0,
       SCALE_ATT, 0);
    softmax_kernel<<<(BB * 1024) / 8, 256, 0, st1>>>(SC, pC, 1024);
    TG(st1, pC, vtC, nullptr, attC, nullptr, 0, gates, 0,
       1024, HH, 1024, 1024, 1024, HH, BB, 1,
       (long)1024 * 1024, 0, (long)HH * 1024, 0, (long)1024 * HH, 0,
       (long)LL * 3, 0, 1.f, 0);
    TG(st1, attC, WoT, O2, nullptr, nullptr, 0, nullptr, 0,
       1024, HH, HH, HH, HH, HH, BB, 1,
       (long)1024 * HH, 0, 0, 0, (long)1024 * HH, 0, 0, 0, 1.f, 0);
    cudaEventRecord(ev1, st1);

    // st0: window branch rest
    TG(st0, qk, qk + 1024, SW, nullptr, nullptr, 0, nullptr, 0,
       WWIN, WWIN, HH, 2048, 2048, WWIN, BB * NWIN, NWIN,
       (long)WTOK * 2048, (long)128 * 2048, (long)WTOK * 2048, (long)128 * 2048,
       (long)NWIN * WWIN * WWIN, (long)WWIN * WWIN, 0, 0, SCALE_ATT, 0);
    softmax_kernel<<<(BB * NWIN * WWIN) / 8, 256, 0, st0>>>(SW, pW, WWIN);
    cudaStreamWaitEvent(st0, evV, 0);
    TG(st0, pW, vt, nullptr, att, nullptr, 0, gates, 2,
       WWIN, HH, WWIN, WWIN, WTOK, HH, BB * NWIN, NWIN,
       (long)NWIN * WWIN * WWIN, (long)WWIN * WWIN, (long)HH * WTOK, 128,
       (long)LL * HH, (long)WWIN * HH, (long)LL * 3, (long)WWIN * 3, 1.f, 0);
    cudaStreamWaitEvent(st0, evWo, 0);
    TG(st0, att, WoT + 2 * HH * HH, O, nullptr, bo, 1, nullptr, 0,
       BB * LL, HH, HH, HH, HH, HH, 1, 1,
       0, 0, 0, 0, 0, 0, 0, 0, 1.f, 0);

    // LN for rows that need only O — before the join
    ln_hi_kernel<<<BB * 3072, 256, 0, st0>>>(O, hs, out);

    // join, then LN for rows needing O2/O3
    cudaStreamWaitEvent(st0, ev1, 0);
    cudaStreamWaitEvent(st0, ev2, 0);
    ln_lo_kernel<<<BB * 1024, 256, 0, st0>>>(O, O2, O3, hs, out);
}

// round 17
// speedup vs baseline: 1.1657x; 1.1657x over previous
#include <cuda_runtime.h>
#include <cuda_fp16.h>
#include <math.h>
#include <stdint.h>

#define BB 4
#define LL 4096
#define HH 1024
#define SELK 512
#define WWIN 256
#define NWIN 16
#define WTOK 2176
#define SCALE_ATT 0.125f

typedef __half h16;

// ---------------- scratch ----------------
__device__ __align__(128) h16  g_hsh[BB * LL * HH];
// window branch
__device__ __align__(128) h16  g_qk[BB * WTOK * 2048];
__device__ __align__(128) h16  g_vt[BB * WTOK * HH];
__device__ __align__(128) float g_SW[BB * NWIN * WWIN * WWIN];
__device__ __align__(128) h16  g_pW[BB * NWIN * WWIN * WWIN];
__device__ __align__(128) h16  g_att[BB * LL * HH];
__device__ __align__(128) float g_O[BB * LL * HH];
// compressed branch
__device__ __align__(128) h16  g_comp[BB * 1024 * HH];
__device__ __align__(128) h16  g_qkC[BB * 1024 * 2048];
__device__ __align__(128) h16  g_vtC[BB * HH * 1024];
__device__ __align__(128) float g_SC[BB * 1024 * 1024];
__device__ __align__(128) h16  g_pC[BB * 1024 * 1024];
__device__ __align__(128) h16  g_attC[BB * 1024 * HH];
__device__ __align__(128) float g_O2[BB * 1024 * HH];
// selected branch
__device__ __align__(128) h16  g_sel[BB * SELK * HH];
__device__ __align__(128) h16  g_qkS[BB * SELK * 2048];
__device__ __align__(128) h16  g_vtS[BB * HH * SELK];
__device__ __align__(128) float g_SS[BB * SELK * SELK];
__device__ __align__(128) h16  g_pS[BB * SELK * SELK];
__device__ __align__(128) h16  g_attS[BB * SELK * HH];
__device__ __align__(128) float g_O3[BB * SELK * HH];
// misc
__device__ __align__(128) float g_gates[BB * LL * 3];
__device__ __align__(128) float g_scr[BB * LL];
__device__ __align__(128) int   g_idx[BB * SELK];
__device__ __align__(128) h16  g_WqkT[2 * HH * HH];
__device__ __align__(128) float g_bqk[2 * HH];
__device__ __align__(128) h16  g_WvT[HH * HH];
__device__ __align__(128) h16  g_WoT[3 * HH * HH];
__device__ __align__(128) h16  g_WcT[4 * HH * HH];

// ---------------- PTX helpers ----------------
__device__ __forceinline__ uint32_t smem_u32(const void* p) {
    uint32_t a;
    asm("{ .reg .u64 t; cvta.to.shared.u64 t, %1; cvt.u32.u64 %0, t; }" : "=r"(a) : "l"(p));
    return a;
}
#define LDSM4(r, a) \
    asm volatile("ldmatrix.sync.aligned.m8n8.x4.shared.b16 {%0,%1,%2,%3}, [%4];" \
        : "=r"((r)[0]), "=r"((r)[1]), "=r"((r)[2]), "=r"((r)[3]) : "r"(a))
#define MMAF16(c, a, b0, b1) \
    asm volatile("mma.sync.aligned.m16n8k16.row.col.f32.f16.f16.f32 " \
        "{%0,%1,%2,%3}, {%4,%5,%6,%7}, {%8,%9}, {%0,%1,%2,%3};" \
        : "+f"((c)[0]), "+f"((c)[1]), "+f"((c)[2]), "+f"((c)[3]) \
        : "r"((a)[0]), "r"((a)[1]), "r"((a)[2]), "r"((a)[3]), "r"(b0), "r"(b1))
#define CP16(s, g) asm volatile("cp.async.cg.shared.global [%0], [%1], 16;" :: "r"(s), "l"(g))
#define CP_COMMIT() asm volatile("cp.async.commit_group;" ::: "memory")
#define CP_WAIT1()  asm volatile("cp.async.wait_group 1;" ::: "memory")
#define CP_WAIT0()  asm volatile("cp.async.wait_group 0;" ::: "memory")

// ---------------- fp16 tensor GEMM via mma.sync (KC=64, 2 CTAs/SM) ----------------
#define KC 64
#define ROWB 144
#define MATB (128 * ROWB)
#define STAGEB (2 * MATB)
#define SMEM_DYN (3 * STAGEB)

__global__ __launch_bounds__(256, 2)
void tgemm_kernel(const h16* __restrict__ A, const h16* __restrict__ B,
                  float* __restrict__ C, h16* __restrict__ Ch,
                  const float* __restrict__ bias, int biasMode,
                  const float* __restrict__ gates, int gateCol,
                  int K, int lda, int ldb, int ldc, int inner,
                  long sA1, long sA2, long sB1, long sB2, long sC1, long sC2,
                  long sG1, long sG2, float scale, int accFlag)
{
    extern __shared__ __align__(128) char dsm[];
    const int tid = threadIdx.x;
    const int wid = tid >> 5, lane = tid & 31;
    const int z = blockIdx.z, zo = z / inner, zi = z - zo * inner;
    A += zo * sA1 + zi * sA2;
    B += zo * sB1 + zi * sB2;
    const long cOff = zo * sC1 + zi * sC2;
    const long gOff = zo * sG1 + zi * sG2;
    const int m0 = blockIdx.y * 128, n0 = blockIdx.x * 128;

    const uint32_t sbase = smem_u32(dsm);
    const int mw = wid >> 2, nw = wid & 3;
    const int m_base = mw * 64, n_base = nw * 32;

    float acc[4][4][4];
#pragma unroll
    for (int i = 0; i < 4; i++)
#pragma unroll
        for (int j = 0; j < 4; j++)
#pragma unroll
            for (int c = 0; c < 4; c++) acc[i][j][c] = 0.f;

    const int nc = K / KC;

    auto load_chunk = [&](int ch, int s) {
        const int kt = ch * KC;
        const uint32_t sb = sbase + s * STAGEB;
#pragma unroll
        for (int it = 0; it < 8; it++) {
            const int idx = it * 256 + tid;
            const int mat = idx >> 10;
            const int rem = idx & 1023;
            const int r = rem >> 3, j = rem & 7;
            const h16* src = mat ? (B + (long)(n0 + r) * ldb + kt + j * 8)
                                 : (A + (long)(m0 + r) * lda + kt + j * 8);
            CP16(sb + mat * MATB + r * ROWB + j * 16, src);
        }
    };

    load_chunk(0, 0);
    CP_COMMIT();
    if (nc > 1) { load_chunk(1, 1); CP_COMMIT(); }

    const uint32_t aOff = (uint32_t)((m_base + (lane & 15)) * ROWB + (lane >> 4) * 16);
    const uint32_t bOff = (uint32_t)((n_base + (lane & 7) + (((lane >> 4) & 1) << 3)) * ROWB
                                     + ((lane >> 3) & 1) * 16);

    for (int ch = 0; ch < nc; ch++) {
        const int s = ch - (ch / 3) * 3;
        if (ch + 1 < nc) CP_WAIT1(); else CP_WAIT0();
        __syncthreads();
        if (ch + 2 < nc) {
            load_chunk(ch + 2, (ch + 2) - ((ch + 2) / 3) * 3);
            CP_COMMIT();
        }
        const uint32_t aB = sbase + s * STAGEB + aOff;
        const uint32_t bB = sbase + s * STAGEB + MATB + bOff;
#pragma unroll
        for (int ks = 0; ks < 4; ks++) {
            uint32_t ah[4][4], bh[2][4];
#pragma unroll
            for (int mt = 0; mt < 4; mt++)
                LDSM4(ah[mt], aB + mt * (16 * ROWB) + ks * 32);
#pragma unroll
            for (int g = 0; g < 2; g++)
                LDSM4(bh[g], bB + g * (16 * ROWB) + ks * 32);
#pragma unroll
            for (int mt = 0; mt < 4; mt++)
#pragma unroll
                for (int nt = 0; nt < 4; nt++) {
                    const int g = nt >> 1, o = (nt & 1) << 1;
                    MMAF16(acc[mt][nt], ah[mt], bh[g][o], bh[g][o + 1]);
                }
        }
    }

    // epilogue
    const int tq = lane & 3, rq = lane >> 2;
#pragma unroll
    for (int mt = 0; mt < 4; mt++) {
#pragma unroll
        for (int half = 0; half < 2; half++) {
            const int rl = m0 + m_base + mt * 16 + rq + half * 8;
            float g = 1.f;
            if (gates) g = gates[gOff + (long)rl * 3 + gateCol];
            float rb = 0.f;
            if (biasMode == 2) rb = bias[rl];
#pragma unroll
            for (int nt = 0; nt < 4; nt++) {
                const int cl = n_base + nt * 8 + tq * 2;
                float v0 = acc[mt][nt][half * 2 + 0] * scale * g;
                float v1 = acc[mt][nt][half * 2 + 1] * scale * g;
                if (biasMode == 1) { v0 += bias[n0 + cl]; v1 += bias[n0 + cl + 1]; }
                else if (biasMode == 2) { v0 += rb; v1 += rb; }
                const long co = cOff + (long)rl * ldc + n0 + cl;
                if (C) {
                    if (accFlag) {
                        const float2 o = *(const float2*)(C + co);
                        v0 += o.x; v1 += o.y;
                    }
                    float2 w; w.x = v0; w.y = v1;
                    *(float2*)(C + co) = w;
                }
                if (Ch) {
                    __align__(4) h16 hv[2];
                    hv[0] = __float2half_rn(v0);
                    hv[1] = __float2half_rn(v1);
                    *(uint32_t*)(Ch + co) = *(uint32_t*)hv;
                }
            }
        }
    }
}

// ---------------- reductions ----------------
__device__ __forceinline__ float warp_sum(float v) {
#pragma unroll
    for (int o = 16; o > 0; o >>= 1) v += __shfl_xor_sync(0xffffffffu, v, o);
    return v;
}
__device__ __forceinline__ float warp_max(float v) {
#pragma unroll
    for (int o = 16; o > 0; o >>= 1) v = fmaxf(v, __shfl_xor_sync(0xffffffffu, v, o));
    return v;
}
__device__ __forceinline__ float blk_sum(float v, float* sh) {
    v = warp_sum(v);
    __syncthreads();
    if ((threadIdx.x & 31) == 0) sh[threadIdx.x >> 5] = v;
    __syncthreads();
    float r = 0.f;
    const int nw = blockDim.x >> 5;
    for (int i = 0; i < nw; i++) r += sh[i];
    return r;
}

// ---------------- fused pre ----------------
__global__ __launch_bounds__(256)
void pre_kernel(const float* __restrict__ hs, const float* __restrict__ Wg,
                const float* __restrict__ bg, const float* __restrict__ Ws,
                const float* __restrict__ bs, const float* __restrict__ bq,
                const float* __restrict__ bk, float* __restrict__ gates,
                float* __restrict__ scr, h16* __restrict__ hsh,
                float* __restrict__ bqk)
{
    __shared__ float sW[4 * HH];
    for (int i = threadIdx.x; i < 3 * HH; i += 256) sW[i] = Wg[i];
    for (int i = threadIdx.x; i < HH; i += 256) sW[3 * HH + i] = Ws[i];
    if (blockIdx.x == 0)
        for (int i = threadIdx.x; i < HH; i += 256) { bqk[i] = bq[i]; bqk[HH + i] = bk[i]; }
    __syncthreads();

    const int wid = threadIdx.x >> 5, lane = threadIdx.x & 31;
    const long row = (long)blockIdx.x * 8 + wid;
    const float4* x = (const float4*)(hs + row * HH);
    uint2* y = (uint2*)(hsh + row * HH);
    float a0 = 0, a1 = 0, a2 = 0, as = 0;
#pragma unroll
    for (int k = 0; k < 8; k++) {
        const float4 v = x[lane + k * 32];
        const int e = 4 * (lane + k * 32);
        a0 += v.x * sW[e * 3] + v.y * sW[e * 3 + 3] + v.z * sW[e * 3 + 6] + v.w * sW[e * 3 + 9];
        a1 += v.x * sW[e * 3 + 1] + v.y * sW[e * 3 + 4] + v.z * sW[e * 3 + 7] + v.w * sW[e * 3 + 10];
        a2 += v.x * sW[e * 3 + 2] + v.y * sW[e * 3 + 5] + v.z * sW[e * 3 + 8] + v.w * sW[e * 3 + 11];
        as += v.x * sW[3 * HH + e] + v.y * sW[3 * HH + e + 1]
            + v.z * sW[3 * HH + e + 2] + v.w * sW[3 * HH + e + 3];
        __align__(8) h16 hv[4];
        hv[0] = __float2half_rn(v.x); hv[1] = __float2half_rn(v.y);
        hv[2] = __float2half_rn(v.z); hv[3] = __float2half_rn(v.w);
        y[lane + k * 32] = *(uint2*)hv;
    }
    a0 = warp_sum(a0); a1 = warp_sum(a1); a2 = warp_sum(a2); as = warp_sum(as);
    if (lane == 0) {
        const float g0 = 1.f / (1.f + expf(-(a0 + bg[0])));
        const float g1 = 1.f / (1.f + expf(-(a1 + bg[1])));
        const float g2 = 1.f / (1.f + expf(-(a2 + bg[2])));
        const float s = g0 + g1 + g2 + 1e-6f;
        gates[row * 3 + 0] = g0 / s;
        gates[row * 3 + 1] = g1 / s;
        gates[row * 3 + 2] = g2 / s;
        scr[row] = as + bs[0];
    }
}

__global__ void ttrans_kernel(const float* __restrict__ W, h16* __restrict__ o,
                              int K, int N)
{
    __shared__ float t[32][33];
    const int bx = blockIdx.x * 32;
    const int by = blockIdx.y * 32;
    const int tx = threadIdx.x, ty = threadIdx.y;
#pragma unroll
    for (int j = 0; j < 32; j += 8) t[ty + j][tx] = W[(long)(by + ty + j) * N + bx + tx];
    __syncthreads();
#pragma unroll
    for (int j = 0; j < 32; j += 8)
        o[(long)(bx + ty + j) * K + by + tx] = __float2half_rn(t[tx][ty + j]);
}

__global__ void topk_kernel(const float* __restrict__ score, int* __restrict__ idx)
{
    const int b = blockIdx.x;
    const int tid = threadIdx.x;
    __shared__ unsigned s_key[4096];
    __shared__ int s_cnt;
    __shared__ int s_sA[1024];
    __shared__ int s_sE[1024];

#pragma unroll
    for (int j = 0; j < 4; j++) {
        const int i = tid * 4 + j;
        unsigned u = __float_as_uint(score[b * 4096 + i]);
        u = (u & 0x80000000u) ? ~u : (u | 0x80000000u);
        s_key[i] = u;
    }
    __syncthreads();

    unsigned lo = 0u, hi = 0xFFFFFFFFu;
    while (lo < hi) {
        const unsigned mid = (unsigned)((((unsigned long long)lo + hi) + 1ull) >> 1);
        if (tid == 0) s_cnt = 0;
        __syncthreads();
        int c = 0;
#pragma unroll
        for (int j = 0; j < 4; j++) c += (s_key[tid * 4 + j] >= mid) ? 1 : 0;
#pragma unroll
        for (int o = 16; o > 0; o >>= 1) c += __shfl_xor_sync(0xffffffffu, c, o);
        if ((tid & 31) == 0) atomicAdd(&s_cnt, c);
        __syncthreads();
        if (s_cnt >= SELK) lo = mid; else hi = mid - 1;
        __syncthreads();
    }
    const unsigned T = lo;

    unsigned kv[4];
    int aCnt = 0, eCnt = 0;
#pragma unroll
    for (int j = 0; j < 4; j++) {
        kv[j] = s_key[tid * 4 + j];
        aCnt += (kv[j] > T) ? 1 : 0;
        eCnt += (kv[j] == T) ? 1 : 0;
    }
    s_sA[tid] = aCnt; s_sE[tid] = eCnt;
    __syncthreads();
    for (int off = 1; off < 1024; off <<= 1) {
        const int a = (tid >= off) ? s_sA[tid - off] : 0;
        const int e = (tid >= off) ? s_sE[tid - off] : 0;
        __syncthreads();
        s_sA[tid] += a; s_sE[tid] += e;
        __syncthreads();
    }
    const int totalA = s_sA[1023];
    const int need = SELK - totalA;
    int aBef = s_sA[tid] - aCnt;
    int eBef = s_sE[tid] - eCnt;
#pragma unroll
    for (int j = 0; j < 4; j++) {
        if (kv[j] > T) {
            idx[b * SELK + aBef + (eBef < need ? eBef : need)] = tid * 4 + j;
            aBef++;
        } else if (kv[j] == T) {
            if (eBef < need) idx[b * SELK + aBef + eBef] = tid * 4 + j;
            eBef++;
        }
    }
}

__global__ void gather_kernel(const h16* __restrict__ hsh, const int* __restrict__ idx,
                              h16* __restrict__ sel)
{
    const int r = blockIdx.x, b = blockIdx.y;
    const int src = idx[b * SELK + r];
    const uint2* s = (const uint2*)(hsh + ((long)b * LL + src) * HH);
    uint2* d = (uint2*)(sel + ((long)b * SELK + r) * HH);
    d[threadIdx.x] = s[threadIdx.x];
}

__global__ __launch_bounds__(256)
void softmax_kernel(const float* __restrict__ S, h16* __restrict__ P, int N)
{
    const int nf = N >> 7;
    const int wid = threadIdx.x >> 5, lane = threadIdx.x & 31;
    const long row = (long)blockIdx.x * 8 + wid;
    const float4* p = (const float4*)(S + row * N);
    float4 v[8];
    float mx = -1e30f;
#pragma unroll
    for (int k = 0; k < 8; k++) if (k < nf) {
        v[k] = p[lane + k * 32];
        mx = fmaxf(mx, fmaxf(fmaxf(v[k].x, v[k].y), fmaxf(v[k].z, v[k].w)));
    }
    mx = warp_max(mx);
    float s = 0.f;
#pragma unroll
    for (int k = 0; k < 8; k++) if (k < nf) {
        v[k].x = expf(v[k].x - mx); v[k].y = expf(v[k].y - mx);
        v[k].z = expf(v[k].z - mx); v[k].w = expf(v[k].w - mx);
        s += v[k].x + v[k].y + v[k].z + v[k].w;
    }
    s = warp_sum(s);
    const float inv = 1.f / s;
    uint2* o = (uint2*)(P + row * N);
#pragma unroll
    for (int k = 0; k < 8; k++) if (k < nf) {
        __align__(8) h16 hv[4];
        hv[0] = __float2half_rn(v[k].x * inv); hv[1] = __float2half_rn(v[k].y * inv);
        hv[2] = __float2half_rn(v[k].z * inv); hv[3] = __float2half_rn(v[k].w * inv);
        o[lane + k * 32] = *(uint2*)hv;
    }
}

__device__ __forceinline__ void ln_row(float4 v, float* sh, float4* y4, int t)
{
    float s = v.x + v.y + v.z + v.w;
    s = blk_sum(s, sh);
    const float mu = s * (1.f / HH);
    float q = (v.x - mu) * (v.x - mu) + (v.y - mu) * (v.y - mu)
            + (v.z - mu) * (v.z - mu) + (v.w - mu) * (v.w - mu);
    __syncthreads();
    q = blk_sum(q, sh);
    const float inv = rsqrtf(q * (1.f / HH) + 1e-6f);
    float4 r;
    r.x = (v.x - mu) * inv; r.y = (v.y - mu) * inv;
    r.z = (v.z - mu) * inv; r.w = (v.w - mu) * inv;
    y4[t] = r;
}

__global__ __launch_bounds__(256)
void ln_hi_kernel(const float* __restrict__ O, const float* __restrict__ hs,
                  float* __restrict__ out)
{
    const long blk = blockIdx.x;
    const long b = blk / 3072, r = blk - b * 3072;
    const long row = b * LL + 1024 + r;
    const int t = threadIdx.x;
    __shared__ float sh[8];
    const float4 a = ((const float4*)(O + row * HH))[t];
    const float4 bx = ((const float4*)(hs + row * HH))[t];
    float4 v;
    v.x = a.x * 0.5f + bx.x * 0.5f;
    v.y = a.y * 0.5f + bx.y * 0.5f;
    v.z = a.z * 0.5f + bx.z * 0.5f;
    v.w = a.w * 0.5f + bx.w * 0.5f;
    ln_row(v, sh, (float4*)(out + row * HH), t);
}

__global__ __launch_bounds__(256)
void ln_lo_kernel(const float* __restrict__ O, const float* __restrict__ O2,
                  const float* __restrict__ O3, const float* __restrict__ hs,
                  float* __restrict__ out)
{
    const long blk = blockIdx.x;
    const long b = blk >> 10, l = blk & 1023;
    const long row = b * LL + l;
    const int t = threadIdx.x;
    __shared__ float sh[8];
    float4 a = ((const float4*)(O + row * HH))[t];
    {
        const float4 c = ((const float4*)(O2 + (b * 1024 + l) * HH))[t];
        a.x += c.x; a.y += c.y; a.z += c.z; a.w += c.w;
    }
    if (l < 512) {
        const float4 c = ((const float4*)(O3 + (b * 512 + l) * HH))[t];
        a.x += c.x; a.y += c.y; a.z += c.z; a.w += c.w;
    }
    const float4 bx = ((const float4*)(hs + row * HH))[t];
    float4 v;
    v.x = a.x * 0.5f + bx.x * 0.5f;
    v.y = a.y * 0.5f + bx.y * 0.5f;
    v.z = a.z * 0.5f + bx.z * 0.5f;
    v.w = a.w * 0.5f + bx.w * 0.5f;
    ln_row(v, sh, (float4*)(out + row * HH), t);
}

// ---------------- host dispatch ----------------
static void TG(cudaStream_t st, const h16* A, const h16* B, float* C, h16* Ch,
               const float* bias, int biasMode, const float* gates, int gateCol,
               int M, int N, int K, int lda, int ldb, int ldc, int nz, int inner,
               long sA1, long sA2, long sB1, long sB2, long sC1, long sC2,
               long sG1, long sG2, float scale, int acc)
{
    dim3 grid(N / 128, M / 128, nz);
    tgemm_kernel<<<grid, 256, SMEM_DYN, st>>>(A, B, C, Ch, bias, biasMode, gates, gateCol,
                                              K, lda, ldb, ldc, inner,
                                              sA1, sA2, sB1, sB2, sC1, sC2,
                                              sG1, sG2, scale, acc);
}

extern "C" void kernel_launch(void* const* d_in, const int* in_sizes, int n_in,
                              void* d_out, int out_size)
{
    const float* hs = (const float*)d_in[0];
    const float* Wq = (const float*)d_in[1];
    const float* bq = (const float*)d_in[2];
    const float* Wk = (const float*)d_in[3];
    const float* bk = (const float*)d_in[4];
    const float* Wv = (const float*)d_in[5];
    const float* bv = (const float*)d_in[6];
    const float* Wo = (const float*)d_in[7];
    const float* bo = (const float*)d_in[8];
    const float* Wg = (const float*)d_in[9];
    const float* bg = (const float*)d_in[10];
    const float* Wc = (const float*)d_in[11];
    const float* bc = (const float*)d_in[12];
    const float* Ws = (const float*)d_in[13];
    const float* bs = (const float*)d_in[14];
    float* out = (float*)d_out;

    static int inited = 0;
    static cudaStream_t st1, st2;
    static cudaEvent_t evS, evPre, evQK, evWv, evWo, evV, evComp, evVtC, ev1, ev2;
    if (!inited) {
        cudaFuncSetAttribute(tgemm_kernel, cudaFuncAttributeMaxDynamicSharedMemorySize, SMEM_DYN);
        cudaStreamCreateWithFlags(&st1, cudaStreamNonBlocking);
        cudaStreamCreateWithFlags(&st2, cudaStreamNonBlocking);
        cudaEventCreateWithFlags(&evS, cudaEventDisableTiming);
        cudaEventCreateWithFlags(&evPre, cudaEventDisableTiming);
        cudaEventCreateWithFlags(&evQK, cudaEventDisableTiming);
        cudaEventCreateWithFlags(&evWv, cudaEventDisableTiming);
        cudaEventCreateWithFlags(&evWo, cudaEventDisableTiming);
        cudaEventCreateWithFlags(&evV, cudaEventDisableTiming);
        cudaEventCreateWithFlags(&evComp, cudaEventDisableTiming);
        cudaEventCreateWithFlags(&evVtC, cudaEventDisableTiming);
        cudaEventCreateWithFlags(&ev1, cudaEventDisableTiming);
        cudaEventCreateWithFlags(&ev2, cudaEventDisableTiming);
        inited = 1;
    }
    cudaStream_t st0 = 0;

    h16 *hsh, *qk, *vt, *pW, *att, *comp, *qkC, *vtC, *pC, *attC;
    h16 *sel, *qkS, *vtS, *pS, *attS, *WqkT, *WvT, *WoT, *WcT;
    float *SW, *SC, *SS, *O, *O2, *O3, *gates, *scr, *bqk;
    int* idx;
    cudaGetSymbolAddress((void**)&hsh, g_hsh);
    cudaGetSymbolAddress((void**)&qk, g_qk);
    cudaGetSymbolAddress((void**)&vt, g_vt);
    cudaGetSymbolAddress((void**)&SW, g_SW);
    cudaGetSymbolAddress((void**)&pW, g_pW);
    cudaGetSymbolAddress((void**)&att, g_att);
    cudaGetSymbolAddress((void**)&O, g_O);
    cudaGetSymbolAddress((void**)&comp, g_comp);
    cudaGetSymbolAddress((void**)&qkC, g_qkC);
    cudaGetSymbolAddress((void**)&vtC, g_vtC);
    cudaGetSymbolAddress((void**)&SC, g_SC);
    cudaGetSymbolAddress((void**)&pC, g_pC);
    cudaGetSymbolAddress((void**)&attC, g_attC);
    cudaGetSymbolAddress((void**)&O2, g_O2);
    cudaGetSymbolAddress((void**)&sel, g_sel);
    cudaGetSymbolAddress((void**)&qkS, g_qkS);
    cudaGetSymbolAddress((void**)&vtS, g_vtS);
    cudaGetSymbolAddress((void**)&SS, g_SS);
    cudaGetSymbolAddress((void**)&pS, g_pS);
    cudaGetSymbolAddress((void**)&attS, g_attS);
    cudaGetSymbolAddress((void**)&O3, g_O3);
    cudaGetSymbolAddress((void**)&gates, g_gates);
    cudaGetSymbolAddress((void**)&scr, g_scr);
    cudaGetSymbolAddress((void**)&idx, g_idx);
    cudaGetSymbolAddress((void**)&WqkT, g_WqkT);
    cudaGetSymbolAddress((void**)&bqk, g_bqk);
    cudaGetSymbolAddress((void**)&WvT, g_WvT);
    cudaGetSymbolAddress((void**)&WoT, g_WoT);
    cudaGetSymbolAddress((void**)&WcT, g_WcT);

    dim3 tb(32, 8);
    // legal fork
    cudaEventRecord(evS, st0);
    cudaStreamWaitEvent(st1, evS, 0);
    cudaStreamWaitEvent(st2, evS, 0);

    // st1: weight transposes first (off critical path)
    ttrans_kernel<<<dim3(HH / 32, HH / 32), tb, 0, st1>>>(Wq, WqkT, HH, HH);
    ttrans_kernel<<<dim3(HH / 32, HH / 32), tb, 0, st1>>>(Wk, WqkT + HH * HH, HH, HH);
    cudaEventRecord(evQK, st1);
    for (int r = 0; r < 3; r++)
        ttrans_kernel<<<dim3(HH / 32, HH / 32), tb, 0, st1>>>(Wo + (long)r * HH * HH,
                                                              WoT + (long)r * HH * HH, HH, HH);
    cudaEventRecord(evWo, st1);
    ttrans_kernel<<<dim3(HH / 32, 4 * HH / 32), tb, 0, st1>>>(Wc, WcT, 4 * HH, HH);

    // st2: Wv transpose
    ttrans_kernel<<<dim3(HH / 32, HH / 32), tb, 0, st2>>>(Wv, WvT, HH, HH);
    cudaEventRecord(evWv, st2);

    // st0: ONLY pre on the critical-path head
    pre_kernel<<<(BB * LL) / 8, 256, 0, st0>>>(hs, Wg, bg, Ws, bs, bq, bk, gates, scr, hsh, bqk);
    cudaEventRecord(evPre, st0);

    // st0: window QK GEMM
    cudaStreamWaitEvent(st0, evQK, 0);
    TG(st0, hsh, WqkT, nullptr, qk, bqk, 1, nullptr, 0,
       WTOK, 2048, HH, HH, HH, 2048, BB, 1,
       (long)LL * HH, 0, 0, 0, (long)WTOK * 2048, 0, 0, 0, 1.f, 0);

    // st1: comp branch head
    cudaStreamWaitEvent(st1, evPre, 0);
    TG(st1, hsh, WcT, nullptr, comp, bc, 1, nullptr, 0,
       BB * 1024, HH, 4 * HH, 4 * HH, 4 * HH, HH, 1, 1,
       0, 0, 0, 0, 0, 0, 0, 0, 1.f, 0);
    cudaEventRecord(evComp, st1);
    TG(st1, comp, WqkT, nullptr, qkC, bqk, 1, nullptr, 0,
       BB * 1024, 2048, HH, HH, HH, 2048, 1, 1, 0, 0, 0, 0, 0, 0, 0, 0, 1.f, 0);
    TG(st1, qkC, qkC + 1024, SC, nullptr, nullptr, 0, nullptr, 0,
       1024, 1024, HH, 2048, 2048, 1024, BB, 1,
       (long)1024 * 2048, 0, (long)1024 * 2048, 0, (long)1024 * 1024, 0, 0, 0,
       SCALE_ATT, 0);
    softmax_kernel<<<(BB * 1024) / 8, 256, 0, st1>>>(SC, pC, 1024);

    // st2: window V, topk/gather, sel-QK, then vtC (comp's V, offloaded)
    cudaStreamWaitEvent(st2, evPre, 0);
    TG(st2, WvT, hsh, nullptr, vt, bv, 2, nullptr, 0,
       HH, WTOK, HH, HH, HH, WTOK, BB, 1,
       0, 0, (long)LL * HH, 0, (long)HH * WTOK, 0, 0, 0, 1.f, 0);
    cudaEventRecord(evV, st2);
    topk_kernel<<<BB, 1024, 0, st2>>>(scr, idx);
    gather_kernel<<<dim3(SELK, BB), 256, 0, st2>>>(hsh, idx, sel);
    cudaStreamWaitEvent(st2, evQK, 0);
    TG(st2, sel, WqkT, nullptr, qkS, bqk, 1, nullptr, 0,
       BB * SELK, 2048, HH, HH, HH, 2048, 1, 1, 0, 0, 0, 0, 0, 0, 0, 0, 1.f, 0);
    TG(st2, WvT, sel, nullptr, vtS, bv, 2, nullptr, 0,
       HH, SELK, HH, HH, HH, SELK, BB, 1,
       0, 0, (long)SELK * HH, 0, (long)HH * SELK, 0, 0, 0, 1.f, 0);
    cudaStreamWaitEvent(st2, evComp, 0);
    TG(st2, WvT, comp, nullptr, vtC, bv, 2, nullptr, 0,
       HH, 1024, HH, HH, HH, 1024, BB, 1,
       0, 0, (long)1024 * HH, 0, (long)HH * 1024, 0, 0, 0, 1.f, 0);
    cudaEventRecord(evVtC, st2);
    TG(st2, qkS, qkS + 1024, SS, nullptr, nullptr, 0, nullptr, 0,
       SELK, SELK, HH, 2048, 2048, SELK, BB, 1,
       (long)SELK * 2048, 0, (long)SELK * 2048, 0, (long)SELK * SELK, 0, 0, 0,
       SCALE_ATT, 0);
    softmax_kernel<<<(BB * SELK) / 8, 256, 0, st2>>>(SS, pS, SELK);
    TG(st2, pS, vtS, nullptr, attS, nullptr, 0, gates, 1,
       SELK, HH, SELK, SELK, SELK, HH, BB, 1,
       (long)SELK * SELK, 0, (long)HH * SELK, 0, (long)SELK * HH, 0,
       (long)LL * 3, 0, 1.f, 0);
    cudaStreamWaitEvent(st2, evWo, 0);
    TG(st2, attS, WoT + HH * HH, O3, nullptr, nullptr, 0, nullptr, 0,
       SELK, HH, HH, HH, HH, HH, BB, 1,
       (long)SELK * HH, 0, 0, 0, (long)SELK * HH, 0, 0, 0, 1.f, 0);
    cudaEventRecord(ev2, st2);

    // st1: comp branch tail (PV needs vtC from st2)
    cudaStreamWaitEvent(st1, evVtC, 0);
    TG(st1, pC, vtC, nullptr, attC, nullptr, 0, gates, 0,
       1024, HH, 1024, 1024, 1024, HH, BB, 1,
       (long)1024 * 1024, 0, (long)HH * 1024, 0, (long)1024 * HH, 0,
       (long)LL * 3, 0, 1.f, 0);
    TG(st1, attC, WoT, O2, nullptr, nullptr, 0, nullptr, 0,
       1024, HH, HH, HH, HH, HH, BB, 1,
       (long)1024 * HH, 0, 0, 0, (long)1024 * HH, 0, 0, 0, 1.f, 0);
    cudaEventRecord(ev1, st1);

    // st0: window branch rest
    TG(st0, qk, qk + 1024, SW, nullptr, nullptr, 0, nullptr, 0,
       WWIN, WWIN, HH, 2048, 2048, WWIN, BB * NWIN, NWIN,
       (long)WTOK * 2048, (long)128 * 2048, (long)WTOK * 2048, (long)128 * 2048,
       (long)NWIN * WWIN * WWIN, (long)WWIN * WWIN, 0, 0, SCALE_ATT, 0);
    softmax_kernel<<<(BB * NWIN * WWIN) / 8, 256, 0, st0>>>(SW, pW, WWIN);
    cudaStreamWaitEvent(st0, evV, 0);
    TG(st0, pW, vt, nullptr, att, nullptr, 0, gates, 2,
       WWIN, HH, WWIN, WWIN, WTOK, HH, BB * NWIN, NWIN,
       (long)NWIN * WWIN * WWIN, (long)WWIN * WWIN, (long)HH * WTOK, 128,
       (long)LL * HH, (long)WWIN * HH, (long)LL * 3, (long)WWIN * 3, 1.f, 0);
    cudaStreamWaitEvent(st0, evWo, 0);
    TG(st0, att, WoT + 2 * HH * HH, O, nullptr, bo, 1, nullptr, 0,
       BB * LL, HH, HH, HH, HH, HH, 1, 1,
       0, 0, 0, 0, 0, 0, 0, 0, 1.f, 0);

    // LN for rows that need only O — before the join
    ln_hi_kernel<<<BB * 3072, 256, 0, st0>>>(O, hs, out);

    // join, then LN for rows needing O2/O3
    cudaStreamWaitEvent(st0, ev1, 0);
    cudaStreamWaitEvent(st0, ev2, 0);
    ln_lo_kernel<<<BB * 1024, 256, 0, st0>>>(O, O2, O3, hs, out);
}